// round 11
// baseline (speedup 1.0000x reference)
#include <cuda_runtime.h>
#include <cuda_fp16.h>

// Problem constants
#define BB 64
#define NN 4096
#define DD 256
#define KK 6
#define HH 64
#define CHUNKS 32
#define ROWS_A (NN / CHUNKS)     // 128 rows per block
#define BATCH 64
#define NBATCH (ROWS_A / BATCH)  // 2

// Device scratch (allocation-free rule: __device__ globals)
__device__ __half g_fh[(size_t)BB * NN * DD];      // LN(features) fp16 (128 MB)
__device__ __half g_qkh[BB * 16 * DD];             // qk fp16: rows 0-7 hi, 8-15 lo (swizzled)
__device__ __half g_partUh[BB * KK * CHUNKS * DD]; // partial sums fp16, (b,k)-major
__device__ float g_partS[BB * KK * CHUNKS];        // partial attention mass, (b,k)-major

// ---------------------------------------------------------------------------
// mma / ldmatrix helpers
// ---------------------------------------------------------------------------
__device__ __forceinline__ unsigned sptr(const void* p) {
    return (unsigned)__cvta_generic_to_shared(p);
}
__device__ __forceinline__ void ldsm4(unsigned& r0, unsigned& r1, unsigned& r2,
                                      unsigned& r3, unsigned addr) {
    asm volatile("ldmatrix.sync.aligned.m8n8.x4.shared.b16 {%0,%1,%2,%3}, [%4];"
                 : "=r"(r0), "=r"(r1), "=r"(r2), "=r"(r3) : "r"(addr));
}
__device__ __forceinline__ void ldsm4t(unsigned& r0, unsigned& r1, unsigned& r2,
                                       unsigned& r3, unsigned addr) {
    asm volatile("ldmatrix.sync.aligned.m8n8.x4.trans.shared.b16 {%0,%1,%2,%3}, [%4];"
                 : "=r"(r0), "=r"(r1), "=r"(r2), "=r"(r3) : "r"(addr));
}
__device__ __forceinline__ void ldsm2t(unsigned& r0, unsigned& r1, unsigned addr) {
    asm volatile("ldmatrix.sync.aligned.m8n8.x2.trans.shared.b16 {%0,%1}, [%2];"
                 : "=r"(r0), "=r"(r1) : "r"(addr));
}
__device__ __forceinline__ void mma16816(float* c, unsigned a0, unsigned a1,
                                         unsigned a2, unsigned a3,
                                         unsigned b0, unsigned b1) {
    asm volatile(
        "mma.sync.aligned.m16n8k16.row.col.f32.f16.f16.f32 "
        "{%0,%1,%2,%3}, {%4,%5,%6,%7}, {%8,%9}, {%0,%1,%2,%3};"
        : "+f"(c[0]), "+f"(c[1]), "+f"(c[2]), "+f"(c[3])
        : "r"(a0), "r"(a1), "r"(a2), "r"(a3), "r"(b0), "r"(b1));
}

// ---------------------------------------------------------------------------
// Shared prep phase (used by init_prep only): s_s[0..63] holds slot vector.
// ---------------------------------------------------------------------------
__device__ __forceinline__ void prep_phase(int b, int k, int t,
                                           float* s_s, float* s_q, float* s_st,
                                           const float* __restrict__ ln_g,
                                           const float* __restrict__ ln_b,
                                           const float* __restrict__ Wq,
                                           const float* __restrict__ Wk) {
    if (t < 32) {
        float a = s_s[t], c = s_s[32 + t];
        float s1 = a + c, s2 = a * a + c * c;
#pragma unroll
        for (int off = 16; off > 0; off >>= 1) {
            s1 += __shfl_xor_sync(0xFFFFFFFFu, s1, off);
            s2 += __shfl_xor_sync(0xFFFFFFFFu, s2, off);
        }
        if (t == 0) {
            float mean = s1 * (1.f / HH);
            float var = s2 * (1.f / HH) - mean * mean;
            s_st[0] = mean;
            s_st[1] = rsqrtf(var + 1e-5f);
        }
    }
    __syncthreads();
    if (t < HH) s_s[t] = (s_s[t] - s_st[0]) * s_st[1] * ln_g[t] + ln_b[t];
    __syncthreads();

    {
        int o = t >> 2, q4 = t & 3;
        const float4* w = (const float4*)(Wq + o * HH + q4 * 16);
        const float4* sv = (const float4*)(s_s + q4 * 16);
        float acc = 0.f;
#pragma unroll
        for (int i = 0; i < 4; i++) {
            float4 w4 = w[i], s4 = sv[i];
            acc += w4.x * s4.x + w4.y * s4.y + w4.z * s4.z + w4.w * s4.w;
        }
        acc += __shfl_xor_sync(0xFFFFFFFFu, acc, 1);
        acc += __shfl_xor_sync(0xFFFFFFFFu, acc, 2);
        if (q4 == 0) s_q[o] = acc * 0.125f;
    }
    __syncthreads();

    {
        float a0 = 0.f, a1 = 0.f, a2 = 0.f, a3 = 0.f;
#pragma unroll
        for (int h = 0; h < HH; h += 4) {
            a0 += s_q[h]     * Wk[(h)     * DD + t];
            a1 += s_q[h + 1] * Wk[(h + 1) * DD + t];
            a2 += s_q[h + 2] * Wk[(h + 2) * DD + t];
            a3 += s_q[h + 3] * Wk[(h + 3) * DD + t];
        }
        float val = (a0 + a1) + (a2 + a3);
        __half hi = __float2half_rn(val);
        __half lo = __float2half_rn(val - __half2float(hi));
        int ch = t >> 3, wi = t & 7;
        int rh = k, rl = 8 + k;
        g_qkh[b * 16 * DD + rh * DD + (((ch ^ (rh & 7)) << 3) | wi)] = hi;
        g_qkh[b * 16 * DD + rl * DD + (((ch ^ (rl & 7)) << 3) | wi)] = lo;
    }
}

// ---------------------------------------------------------------------------
// Kernel IP: fused slot init + qk padding zero + first prep. grid (KK, BB).
// ---------------------------------------------------------------------------
__global__ void __launch_bounds__(256)
init_prep_kernel(float* __restrict__ slots,
                 const float* __restrict__ noise,
                 const float* __restrict__ mu,
                 const float* __restrict__ sigma,
                 const float* __restrict__ ln_g,
                 const float* __restrict__ ln_b,
                 const float* __restrict__ Wq,
                 const float* __restrict__ Wk) {
    int k = blockIdx.x, b = blockIdx.y, t = threadIdx.x;
    __shared__ __align__(16) float s_s[HH];
    __shared__ __align__(16) float s_q[HH];
    __shared__ float s_st[2];

    if (k == 0) {  // zero qkh padding rows 6,7,14,15 for this b
        __half z = __ushort_as_half(0);
        g_qkh[b * 16 * DD + 6 * DD + t] = z;
        g_qkh[b * 16 * DD + 7 * DD + t] = z;
        g_qkh[b * 16 * DD + 14 * DD + t] = z;
        g_qkh[b * 16 * DD + 15 * DD + t] = z;
    }
    if (t < HH) {
        float sv = mu[t] + sigma[t] * noise[(b * KK + k) * HH + t];
        slots[(b * KK + k) * HH + t] = sv;
        s_s[t] = sv;
    }
    __syncthreads();
    prep_phase(b, k, t, s_s, s_q, s_st, ln_g, ln_b, Wq, Wk);
}

// ---------------------------------------------------------------------------
// Kernel LN: one-time LN(features) -> fp16. 2 rows per warp.
// ---------------------------------------------------------------------------
__global__ void __launch_bounds__(256)
ln_feat_kernel(const float* __restrict__ feat,
               const float* __restrict__ g,
               const float* __restrict__ bvec) {
    size_t r0 = (size_t)blockIdx.x * 16 + (threadIdx.x >> 5) * 2;
    int lane = threadIdx.x & 31;
    const float* p0 = feat + r0 * DD + 8 * lane;
    float4 a0 = ((const float4*)p0)[0];
    float4 c0 = ((const float4*)p0)[1];
    float4 a1 = ((const float4*)(p0 + DD))[0];
    float4 c1 = ((const float4*)(p0 + DD))[1];
    float f0[8] = {a0.x, a0.y, a0.z, a0.w, c0.x, c0.y, c0.z, c0.w};
    float f1[8] = {a1.x, a1.y, a1.z, a1.w, c1.x, c1.y, c1.z, c1.w};

    float s10 = 0.f, s20 = 0.f, s11 = 0.f, s21 = 0.f;
#pragma unroll
    for (int j = 0; j < 8; j++) {
        s10 += f0[j]; s20 += f0[j] * f0[j];
        s11 += f1[j]; s21 += f1[j] * f1[j];
    }
#pragma unroll
    for (int off = 16; off > 0; off >>= 1) {
        s10 += __shfl_xor_sync(0xFFFFFFFFu, s10, off);
        s20 += __shfl_xor_sync(0xFFFFFFFFu, s20, off);
        s11 += __shfl_xor_sync(0xFFFFFFFFu, s11, off);
        s21 += __shfl_xor_sync(0xFFFFFFFFu, s21, off);
    }
    float m0 = s10 * (1.f / DD), m1 = s11 * (1.f / DD);
    float r0s = rsqrtf(s20 * (1.f / DD) - m0 * m0 + 1e-5f);
    float r1s = rsqrtf(s21 * (1.f / DD) - m1 * m1 + 1e-5f);

    float4 ga = ((const float4*)(g + 8 * lane))[0];
    float4 gc = ((const float4*)(g + 8 * lane))[1];
    float4 ba = ((const float4*)(bvec + 8 * lane))[0];
    float4 bc = ((const float4*)(bvec + 8 * lane))[1];
    float gg[8] = {ga.x, ga.y, ga.z, ga.w, gc.x, gc.y, gc.z, gc.w};
    float bb[8] = {ba.x, ba.y, ba.z, ba.w, bc.x, bc.y, bc.z, bc.w};

    __half2 h0[4], h1[4];
#pragma unroll
    for (int j = 0; j < 4; j++) {
        float x0 = (f0[2 * j] - m0) * r0s * gg[2 * j] + bb[2 * j];
        float y0 = (f0[2 * j + 1] - m0) * r0s * gg[2 * j + 1] + bb[2 * j + 1];
        float x1 = (f1[2 * j] - m1) * r1s * gg[2 * j] + bb[2 * j];
        float y1 = (f1[2 * j + 1] - m1) * r1s * gg[2 * j + 1] + bb[2 * j + 1];
        h0[j] = __float22half2_rn(make_float2(x0, y0));
        h1[j] = __float22half2_rn(make_float2(x1, y1));
    }
    *(uint4*)(g_fh + r0 * DD + 8 * lane) = *(uint4*)h0;
    *(uint4*)(g_fh + (r0 + 1) * DD + 8 * lane) = *(uint4*)h1;
}

// ---------------------------------------------------------------------------
// Kernel A (hot): tensor-core attention streaming pass (round-5 config).
// grid (CHUNKS, BB) = 2048 blocks, 256 threads. 128 rows/block in 2 batches
// of 64; both batches cp.async'd upfront; P1(nb) overlapped with P3(nb-1).
// ---------------------------------------------------------------------------
#define SMEM_F_BYTES (2 * BATCH * DD * 2)
#define SMEM_QK_OFF  SMEM_F_BYTES
#define SMEM_DOT_OFF (SMEM_QK_OFF + 16 * DD * 2)
#define SMEM_A_OFF   (SMEM_DOT_OFF + 2 * BATCH * 8 * 4)
#define SMEM_SP_OFF  (SMEM_A_OFF + 2 * BATCH * 8 * 2)
#define ATTN_SMEM    (SMEM_SP_OFF + 12 * 4)

__device__ __forceinline__ void issue_batch(const __half* gbase, int nb,
                                            char* smem, int tid) {
    const char* g = (const char*)(gbase + (size_t)nb * BATCH * DD);
    unsigned sbase = sptr(smem) + (nb & 1) * (BATCH * DD * 2);
#pragma unroll
    for (int it = 0; it < 8; it++) {
        int idx = tid + it * 256;
        int row = idx >> 5, j = idx & 31;
        unsigned dst = sbase + row * 512 + ((j ^ (row & 7)) << 4);
        const char* src = g + row * 512 + j * 16;
        asm volatile("cp.async.ca.shared.global [%0], [%1], 16;\n"
                     :: "r"(dst), "l"(src));
    }
    asm volatile("cp.async.commit_group;\n");
}

__global__ void __launch_bounds__(256, 2)
attn_kernel() {
    extern __shared__ __align__(16) char smem[];
    __half* s_qk = (__half*)(smem + SMEM_QK_OFF);
    float* s_dot = (float*)(smem + SMEM_DOT_OFF);
    __half* s_a  = (__half*)(smem + SMEM_A_OFF);
    float* s_Sp  = (float*)(smem + SMEM_SP_OFF);

    int b = blockIdx.y, chunk = blockIdx.x;
    int tid = threadIdx.x, w = tid >> 5, lane = tid & 31;

    // load swizzled qk (hi/lo) block: 512 uint4
    {
        const uint4* qs = (const uint4*)(g_qkh + b * 16 * DD);
        uint4* qd = (uint4*)s_qk;
        qd[tid] = qs[tid];
        qd[tid + 256] = qs[tid + 256];
    }

    const __half* gbase = g_fh + ((size_t)b * NN + (size_t)chunk * ROWS_A) * DD;
    issue_batch(gbase, 0, smem, tid);
    issue_batch(gbase, 1, smem, tid);

    unsigned s_f_u  = sptr(smem);
    unsigned s_qk_u = sptr(s_qk);
    unsigned s_a_u  = sptr(s_a);

    float accS[KK];
#pragma unroll
    for (int k = 0; k < KK; k++) accS[k] = 0.f;
    float u0[4] = {0.f, 0.f, 0.f, 0.f};
    float u1[4] = {0.f, 0.f, 0.f, 0.f};

    int g4 = lane >> 2, t4 = lane & 3;

    // P1 fragment index precompute
    int rt = w & 3, kh = w >> 2;
    int r0 = rt * 16;
    int arow = r0 + (lane & 15);
    int asel = lane >> 4;
    int brow = (lane & 7) + ((lane >> 4) << 3);
    int bsel = (lane >> 3) & 1;
    unsigned brow_base = s_qk_u + brow * 512;
    // P3 fragment index precompute
    int trow = (lane & 7) + ((lane >> 4) << 3);
    int tsel = (lane >> 3) & 1;

#pragma unroll
    for (int nb = 0; nb < NBATCH; nb++) {
        if (nb == 0) {
            asm volatile("cp.async.wait_group 1;\n" ::: "memory");
        } else {
            asm volatile("cp.async.wait_group 0;\n" ::: "memory");
        }
        __syncthreads();

        unsigned fb = s_f_u + (nb & 1) * (BATCH * DD * 2);

        // ---- P1: dots via mma on batch nb ----
        {
            float c[4] = {0.f, 0.f, 0.f, 0.f};
            unsigned arow_base = fb + arow * 512;
#pragma unroll
            for (int i = 0; i < 8; i++) {
                int kc = kh * 8 + i;
                unsigned a0, a1, a2, a3, bh0, bh1, bl0, bl1;
                int ach = 2 * kc + asel;
                ldsm4(a0, a1, a2, a3, arow_base + ((ach ^ (arow & 7)) << 4));
                int bch = 2 * kc + bsel;
                ldsm4(bh0, bh1, bl0, bl1, brow_base + ((bch ^ (brow & 7)) << 4));
                mma16816(c, a0, a1, a2, a3, bh0, bh1);
                mma16816(c, a0, a1, a2, a3, bl0, bl1);
            }
            float* dbase = s_dot + kh * (BATCH * 8);
            *(float2*)(dbase + (r0 + g4) * 8 + 2 * t4)     = make_float2(c[0], c[1]);
            *(float2*)(dbase + (r0 + g4 + 8) * 8 + 2 * t4) = make_float2(c[2], c[3]);
        }

        // ---- P3 for previous batch (no barrier needed: disjoint smem) ----
        if (nb > 0) {
            unsigned fp = s_f_u + ((nb - 1) & 1) * (BATCH * DD * 2);
            unsigned ap = s_a_u + ((nb - 1) & 1) * (BATCH * 8 * 2);
#pragma unroll
            for (int kc = 0; kc < 4; kc++) {
                unsigned b0, b1;
                ldsm2t(b0, b1, ap + (kc * 16 + (lane & 15)) * 16);
                int row = kc * 16 + trow;
                unsigned rbase = fp + row * 512;
                {
                    unsigned a0, a1, a2, a3;
                    int ch = w * 2 + tsel;
                    ldsm4t(a0, a1, a2, a3, rbase + ((ch ^ (row & 7)) << 4));
                    mma16816(u0, a0, a1, a2, a3, b0, b1);
                }
                {
                    unsigned a0, a1, a2, a3;
                    int ch = (w + 8) * 2 + tsel;
                    ldsm4t(a0, a1, a2, a3, rbase + ((ch ^ (row & 7)) << 4));
                    mma16816(u1, a0, a1, a2, a3, b0, b1);
                }
            }
        }
        __syncthreads();

        // ---- P2: per-row softmax (threads 0-63), a -> fp16 ----
        if (tid < 64) {
            int r = tid;
            float4 da = ((const float4*)(s_dot + r * 8))[0];
            float4 db = ((const float4*)(s_dot + r * 8))[1];
            float4 ea = ((const float4*)(s_dot + BATCH * 8 + r * 8))[0];
            float4 eb = ((const float4*)(s_dot + BATCH * 8 + r * 8))[1];
            float d[KK] = {da.x + ea.x, da.y + ea.y, da.z + ea.z,
                           da.w + ea.w, db.x + eb.x, db.y + eb.y};
            float mx = d[0];
#pragma unroll
            for (int k = 1; k < KK; k++) mx = fmaxf(mx, d[k]);
            float se = 0.f;
#pragma unroll
            for (int k = 0; k < KK; k++) { d[k] = __expf(d[k] - mx); se += d[k]; }
            float inv = 1.f / se;
            __half h[KK];
#pragma unroll
            for (int k = 0; k < KK; k++) {
                h[k] = __float2half_rn(d[k] * inv);
                accS[k] += __half2float(h[k]);
            }
            unsigned p0 = ((unsigned)__half_as_ushort(h[1]) << 16) | __half_as_ushort(h[0]);
            unsigned p1 = ((unsigned)__half_as_ushort(h[3]) << 16) | __half_as_ushort(h[2]);
            unsigned p2 = ((unsigned)__half_as_ushort(h[5]) << 16) | __half_as_ushort(h[4]);
            *(uint4*)(s_a + (nb & 1) * BATCH * 8 + r * 8) =
                make_uint4(p0, p1, p2, 0u);
        }
        __syncthreads();
    }

    // ---- final P3 for last batch ----
    {
        unsigned fp = s_f_u + ((NBATCH - 1) & 1) * (BATCH * DD * 2);
        unsigned ap = s_a_u + ((NBATCH - 1) & 1) * (BATCH * 8 * 2);
#pragma unroll
        for (int kc = 0; kc < 4; kc++) {
            unsigned b0, b1;
            ldsm2t(b0, b1, ap + (kc * 16 + (lane & 15)) * 16);
            int row = kc * 16 + trow;
            unsigned rbase = fp + row * 512;
            {
                unsigned a0, a1, a2, a3;
                int ch = w * 2 + tsel;
                ldsm4t(a0, a1, a2, a3, rbase + ((ch ^ (row & 7)) << 4));
                mma16816(u0, a0, a1, a2, a3, b0, b1);
            }
            {
                unsigned a0, a1, a2, a3;
                int ch = (w + 8) * 2 + tsel;
                ldsm4t(a0, a1, a2, a3, rbase + ((ch ^ (row & 7)) << 4));
                mma16816(u1, a0, a1, a2, a3, b0, b1);
            }
        }
    }

    // ---- epilogue: write U tiles ((b,k)-major, fp16) and S ----
    {
        if (t4 < 3) {
            int k0 = 2 * t4, k1 = 2 * t4 + 1;
            __half* p0 = g_partUh + ((size_t)(b * KK + k0) * CHUNKS + chunk) * DD;
            __half* p1 = g_partUh + ((size_t)(b * KK + k1) * CHUNKS + chunk) * DD;
            int d0 = w * 16;
            p0[d0 + g4]     = __float2half_rn(u0[0]);
            p1[d0 + g4]     = __float2half_rn(u0[1]);
            p0[d0 + 8 + g4] = __float2half_rn(u0[2]);
            p1[d0 + 8 + g4] = __float2half_rn(u0[3]);
            int d1 = (w + 8) * 16;
            p0[d1 + g4]     = __float2half_rn(u1[0]);
            p1[d1 + g4]     = __float2half_rn(u1[1]);
            p0[d1 + 8 + g4] = __float2half_rn(u1[2]);
            p1[d1 + 8 + g4] = __float2half_rn(u1[3]);
        }
    }
    if (tid < 64) {
#pragma unroll
        for (int off = 16; off > 0; off >>= 1)
#pragma unroll
            for (int k = 0; k < KK; k++)
                accS[k] += __shfl_xor_sync(0xFFFFFFFFu, accS[k], off);
        if (lane == 0)
#pragma unroll
            for (int k = 0; k < KK; k++) s_Sp[w * KK + k] = accS[k];
    }
    __syncthreads();
    if (tid < KK)
        g_partS[(b * KK + tid) * CHUNKS + chunk] = s_Sp[tid] + s_Sp[KK + tid];
}

// ---------------------------------------------------------------------------
// Kernel C: one block per batch b (grid=BB, 256 threads). All 6 slots (k)
// interleaved in every phase (round-10 structure); partU gather now fp16.
// ---------------------------------------------------------------------------
__global__ void __launch_bounds__(256)
update_kernel(float* __restrict__ slots,
              const float* __restrict__ Wv,
              const float* __restrict__ Wih,
              const float* __restrict__ Whh,
              const float* __restrict__ bih,
              const float* __restrict__ bhh,
              const float* __restrict__ lnm_g,
              const float* __restrict__ lnm_b,
              const float* __restrict__ W1,
              const float* __restrict__ b1,
              const float* __restrict__ W2,
              const float* __restrict__ b2,
              const float* __restrict__ lns_g,
              const float* __restrict__ lns_b,
              const float* __restrict__ Wq,
              const float* __restrict__ Wk,
              int do_prep) {
    int b = blockIdx.x, t = threadIdx.x;
    __shared__ __align__(16) float sU[KK][DD];
    __shared__ __align__(16) float sxv[KK][HH];
    __shared__ __align__(16) float shp[KK][HH];
    __shared__ float sgrz[KK][2 * HH];
    __shared__ float sgin[KK][HH], sghn[KK][HH];
    __shared__ __align__(16) float shn[KK][HH];
    __shared__ __align__(16) float smm[KK][HH];
    __shared__ __align__(16) float sm1[KK][2 * HH];
    __shared__ __align__(16) float sout[KK][HH];
    __shared__ float sq[KK][HH];
    __shared__ float sst[KK][4];

    // Phase A: gather fp16 partials (c-ascending order per k)
#pragma unroll
    for (int k = 0; k < KK; k++) {
        const __half* base = g_partUh + (size_t)(b * KK + k) * CHUNKS * DD;
        float u = 0.f;
#pragma unroll
        for (int c = 0; c < CHUNKS; c++)
            u += __half2float(base[c * DD + t]);
        sU[k][t] = u;
    }
    if (t < 192) {
        int k = t >> 5, lane = t & 31;
        float S = g_partS[(b * KK + k) * CHUNKS + lane];
#pragma unroll
        for (int off = 16; off > 0; off >>= 1)
            S += __shfl_xor_sync(0xFFFFFFFFu, S, off);
        if (lane == 0) sst[k][0] = 1.f / (S + 1e-8f);
    }
    for (int i = t; i < KK * HH; i += 256) {
        int k = i >> 6, h = i & 63;
        shp[k][h] = slots[(b * KK + k) * HH + h];
    }
    __syncthreads();

    // Phase B: xv = (Wv @ U) * invS  (4 thr/output; weight loaded once)
    {
        int o = t >> 2, q = t & 3;
        const float4* wv = (const float4*)(Wv + o * DD + q * 64);
        float a0[KK], a1[KK];
#pragma unroll
        for (int k = 0; k < KK; k++) { a0[k] = 0.f; a1[k] = 0.f; }
#pragma unroll
        for (int i = 0; i < 16; i++) {
            float4 w4 = wv[i];
#pragma unroll
            for (int k = 0; k < KK; k++) {
                float4 u4 = ((const float4*)(&sU[k][q * 64]))[i];
                a0[k] += w4.x * u4.x + w4.z * u4.z;
                a1[k] += w4.y * u4.y + w4.w * u4.w;
            }
        }
#pragma unroll
        for (int k = 0; k < KK; k++) {
            float acc = a0[k] + a1[k];
            acc += __shfl_xor_sync(0xFFFFFFFFu, acc, 1);
            acc += __shfl_xor_sync(0xFFFFFFFFu, acc, 2);
            if (q == 0) sxv[k][o] = acc * sst[k][0];
        }
    }
    __syncthreads();

    // Phase C: GRU gate GEMVs (thread = gate row; weights loaded once)
    if (t < 192) {
        int gate = t >> 6, idx = t & 63;
        const float4* wi = (const float4*)(Wih + t * HH);
        const float4* wh = (const float4*)(Whh + t * HH);
        float gi[KK], gh[KK];
        float bi = bih[t], bh = bhh[t];
#pragma unroll
        for (int k = 0; k < KK; k++) { gi[k] = bi; gh[k] = bh; }
#pragma unroll
        for (int i = 0; i < 16; i++) {
            float4 w4 = wi[i], v4 = wh[i];
#pragma unroll
            for (int k = 0; k < KK; k++) {
                float4 x4 = ((const float4*)sxv[k])[i];
                float4 h4 = ((const float4*)shp[k])[i];
                gi[k] += w4.x * x4.x + w4.y * x4.y + w4.z * x4.z + w4.w * x4.w;
                gh[k] += v4.x * h4.x + v4.y * h4.y + v4.z * h4.z + v4.w * h4.w;
            }
        }
#pragma unroll
        for (int k = 0; k < KK; k++) {
            if (gate < 2) sgrz[k][t] = gi[k] + gh[k];
            else { sgin[k][idx] = gi[k]; sghn[k][idx] = gh[k]; }
        }
    }
    __syncthreads();

    // Phase D: gate nonlinearity + h update
    for (int i = t; i < KK * HH; i += 256) {
        int k = i >> 6, h = i & 63;
        float r = 1.f / (1.f + __expf(-sgrz[k][h]));
        float z = 1.f / (1.f + __expf(-sgrz[k][64 + h]));
        float n = tanhf(sgin[k][h] + r * sghn[k][h]);
        shn[k][h] = (1.f - z) * n + z * shp[k][h];
    }
    __syncthreads();

    // LN over new slots (warp per k)
    if (t < 192) {
        int k = t >> 5, lane = t & 31;
        float a = shn[k][lane], c = shn[k][32 + lane];
        float s1 = a + c, s2 = a * a + c * c;
#pragma unroll
        for (int off = 16; off > 0; off >>= 1) {
            s1 += __shfl_xor_sync(0xFFFFFFFFu, s1, off);
            s2 += __shfl_xor_sync(0xFFFFFFFFu, s2, off);
        }
        if (lane == 0) {
            float mean = s1 * (1.f / HH);
            float var = s2 * (1.f / HH) - mean * mean;
            sst[k][1] = mean;
            sst[k][2] = rsqrtf(var + 1e-5f);
        }
    }
    __syncthreads();
    for (int i = t; i < KK * HH; i += 256) {
        int k = i >> 6, h = i & 63;
        smm[k][h] = (shn[k][h] - sst[k][1]) * sst[k][2] * lnm_g[h] + lnm_b[h];
    }
    __syncthreads();

    // Phase E: MLP layer 1 (2 thr/output; weights loaded once)
    {
        int o = t >> 1, hf = t & 1;
        const float4* w1 = (const float4*)(W1 + o * HH + hf * 32);
        float acc[KK];
#pragma unroll
        for (int k = 0; k < KK; k++) acc[k] = 0.f;
#pragma unroll
        for (int i = 0; i < 8; i++) {
            float4 w4 = w1[i];
#pragma unroll
            for (int k = 0; k < KK; k++) {
                float4 m4 = ((const float4*)(&smm[k][hf * 32]))[i];
                acc[k] += w4.x * m4.x + w4.y * m4.y + w4.z * m4.z + w4.w * m4.w;
            }
        }
        float bo = b1[o];
#pragma unroll
        for (int k = 0; k < KK; k++) {
            float a = acc[k];
            a += __shfl_xor_sync(0xFFFFFFFFu, a, 1);
            if (hf == 0) sm1[k][o] = fmaxf(a + bo, 0.f);
        }
    }
    __syncthreads();

    // Phase F: MLP layer 2 + residual
    {
        int o = t >> 2, q = t & 3;
        const float4* w2 = (const float4*)(W2 + o * 2 * HH + q * 32);
        float acc[KK];
#pragma unroll
        for (int k = 0; k < KK; k++) acc[k] = 0.f;
#pragma unroll
        for (int i = 0; i < 8; i++) {
            float4 w4 = w2[i];
#pragma unroll
            for (int k = 0; k < KK; k++) {
                float4 m4 = ((const float4*)(&sm1[k][q * 32]))[i];
                acc[k] += w4.x * m4.x + w4.y * m4.y + w4.z * m4.z + w4.w * m4.w;
            }
        }
        float bo = b2[o];
#pragma unroll
        for (int k = 0; k < KK; k++) {
            float a = acc[k];
            a += __shfl_xor_sync(0xFFFFFFFFu, a, 1);
            a += __shfl_xor_sync(0xFFFFFFFFu, a, 2);
            if (q == 0) {
                float out = shn[k][o] + a + bo;
                slots[(b * KK + k) * HH + o] = out;
                sout[k][o] = out;
            }
        }
    }

    if (!do_prep) return;
    __syncthreads();

    // ---- fused prep: LN(slots) -> q = Wq@s*0.125 -> qk hi/lo ----
    if (t < 192) {
        int k = t >> 5, lane = t & 31;
        float a = sout[k][lane], c = sout[k][32 + lane];
        float s1 = a + c, s2 = a * a + c * c;
#pragma unroll
        for (int off = 16; off > 0; off >>= 1) {
            s1 += __shfl_xor_sync(0xFFFFFFFFu, s1, off);
            s2 += __shfl_xor_sync(0xFFFFFFFFu, s2, off);
        }
        if (lane == 0) {
            float mean = s1 * (1.f / HH);
            float var = s2 * (1.f / HH) - mean * mean;
            sst[k][1] = mean;
            sst[k][2] = rsqrtf(var + 1e-5f);
        }
    }
    __syncthreads();
    for (int i = t; i < KK * HH; i += 256) {
        int k = i >> 6, h = i & 63;
        smm[k][h] = (sout[k][h] - sst[k][1]) * sst[k][2] * lns_g[h] + lns_b[h];
    }
    __syncthreads();

    {
        int o = t >> 2, q4 = t & 3;
        const float4* w = (const float4*)(Wq + o * HH + q4 * 16);
        float acc[KK];
#pragma unroll
        for (int k = 0; k < KK; k++) acc[k] = 0.f;
#pragma unroll
        for (int i = 0; i < 4; i++) {
            float4 w4 = w[i];
#pragma unroll
            for (int k = 0; k < KK; k++) {
                float4 s4 = ((const float4*)(&smm[k][q4 * 16]))[i];
                acc[k] += w4.x * s4.x + w4.y * s4.y + w4.z * s4.z + w4.w * s4.w;
            }
        }
#pragma unroll
        for (int k = 0; k < KK; k++) {
            float a = acc[k];
            a += __shfl_xor_sync(0xFFFFFFFFu, a, 1);
            a += __shfl_xor_sync(0xFFFFFFFFu, a, 2);
            if (q4 == 0) sq[k][o] = a * 0.125f;
        }
    }
    __syncthreads();

    {
        float a0[KK], a1[KK], a2[KK], a3[KK];
#pragma unroll
        for (int k = 0; k < KK; k++) { a0[k] = 0.f; a1[k] = 0.f; a2[k] = 0.f; a3[k] = 0.f; }
#pragma unroll
        for (int h = 0; h < HH; h += 4) {
            float wk0 = Wk[(h)     * DD + t];
            float wk1 = Wk[(h + 1) * DD + t];
            float wk2 = Wk[(h + 2) * DD + t];
            float wk3 = Wk[(h + 3) * DD + t];
#pragma unroll
            for (int k = 0; k < KK; k++) {
                a0[k] += sq[k][h]     * wk0;
                a1[k] += sq[k][h + 1] * wk1;
                a2[k] += sq[k][h + 2] * wk2;
                a3[k] += sq[k][h + 3] * wk3;
            }
        }
        int ch = t >> 3, wi = t & 7;
#pragma unroll
        for (int k = 0; k < KK; k++) {
            float val = (a0[k] + a1[k]) + (a2[k] + a3[k]);
            __half hi = __float2half_rn(val);
            __half lo = __float2half_rn(val - __half2float(hi));
            int rh = k, rl = 8 + k;
            g_qkh[b * 16 * DD + rh * DD + (((ch ^ (rh & 7)) << 3) | wi)] = hi;
            g_qkh[b * 16 * DD + rl * DD + (((ch ^ (rl & 7)) << 3) | wi)] = lo;
        }
    }
}

// ---------------------------------------------------------------------------
extern "C" void kernel_launch(void* const* d_in, const int* in_sizes, int n_in,
                              void* d_out, int out_size) {
    const float* features   = (const float*)d_in[0];
    const float* slot_noise = (const float*)d_in[1];
    const float* slot_mu    = (const float*)d_in[2];
    const float* slot_sigma = (const float*)d_in[3];
    const float* ln_feat_g  = (const float*)d_in[4];
    const float* ln_feat_b  = (const float*)d_in[5];
    const float* ln_slot_g  = (const float*)d_in[6];
    const float* ln_slot_b  = (const float*)d_in[7];
    const float* ln_mlp_g   = (const float*)d_in[8];
    const float* ln_mlp_b   = (const float*)d_in[9];
    const float* Wk         = (const float*)d_in[10];
    const float* Wv         = (const float*)d_in[11];
    const float* Wq         = (const float*)d_in[12];
    const float* W_ih       = (const float*)d_in[13];
    const float* W_hh       = (const float*)d_in[14];
    const float* b_ih       = (const float*)d_in[15];
    const float* b_hh       = (const float*)d_in[16];
    const float* mlp_W1     = (const float*)d_in[17];
    const float* mlp_b1     = (const float*)d_in[18];
    const float* mlp_W2     = (const float*)d_in[19];
    const float* mlp_b2     = (const float*)d_in[20];

    float* slots = (float*)d_out;  // [B, K, H] lives in the output buffer

    cudaFuncSetAttribute(attn_kernel,
                         cudaFuncAttributeMaxDynamicSharedMemorySize,
                         ATTN_SMEM);

    dim3 gridSmall(KK, BB);
    dim3 gridA(CHUNKS, BB);

    init_prep_kernel<<<gridSmall, 256>>>(slots, slot_noise, slot_mu, slot_sigma,
                                         ln_slot_g, ln_slot_b, Wq, Wk);
    ln_feat_kernel<<<BB * NN / 16, 256>>>(features, ln_feat_g, ln_feat_b);

    for (int it = 0; it < 3; it++) {
        attn_kernel<<<gridA, 256, ATTN_SMEM>>>();
        update_kernel<<<BB, 256>>>(slots, Wv, W_ih, W_hh, b_ih, b_hh,
                                   ln_mlp_g, ln_mlp_b, mlp_W1, mlp_b1,
                                   mlp_W2, mlp_b2, ln_slot_g, ln_slot_b,
                                   Wq, Wk, it < 2 ? 1 : 0);
    }
}

// round 12
// speedup vs baseline: 1.0458x; 1.0458x over previous
#include <cuda_runtime.h>
#include <cuda_fp16.h>

// Problem constants
#define BB 64
#define NN 4096
#define DD 256
#define KK 6
#define HH 64
#define CHUNKS 32
#define ROWS_A (NN / CHUNKS)     // 128 rows per block
#define BATCH 64
#define NBATCH (ROWS_A / BATCH)  // 2

// Device scratch (allocation-free rule: __device__ globals)
__device__ __half g_fh[(size_t)BB * NN * DD];     // LN(features) fp16 (128 MB)
__device__ __half g_qkh[BB * 16 * DD];            // qk fp16: rows 0-7 hi, 8-15 lo (swizzled)
__device__ float g_partU[BB * KK * CHUNKS * DD];  // partial sums, (b,k)-major contiguous
__device__ float g_partS[BB * KK * CHUNKS];       // partial attention mass, (b,k)-major

// ---------------------------------------------------------------------------
// PDL / prefetch helpers
// ---------------------------------------------------------------------------
__device__ __forceinline__ void griddep_wait() {
    asm volatile("griddepcontrol.wait;" ::: "memory");
}
__device__ __forceinline__ void griddep_launch_dependents() {
    asm volatile("griddepcontrol.launch_dependents;" ::: "memory");
}
__device__ __forceinline__ void l2_prefetch(const void* p) {
    asm volatile("prefetch.global.L2 [%0];" :: "l"(p));
}
__device__ __forceinline__ void prefetch_array(const float* a, int n, int t,
                                               int nthreads) {
    for (int i = t * 32; i < n; i += nthreads * 32) l2_prefetch(a + i);
}

// ---------------------------------------------------------------------------
// mma / ldmatrix helpers
// ---------------------------------------------------------------------------
__device__ __forceinline__ unsigned sptr(const void* p) {
    return (unsigned)__cvta_generic_to_shared(p);
}
__device__ __forceinline__ void ldsm4(unsigned& r0, unsigned& r1, unsigned& r2,
                                      unsigned& r3, unsigned addr) {
    asm volatile("ldmatrix.sync.aligned.m8n8.x4.shared.b16 {%0,%1,%2,%3}, [%4];"
                 : "=r"(r0), "=r"(r1), "=r"(r2), "=r"(r3) : "r"(addr));
}
__device__ __forceinline__ void ldsm4t(unsigned& r0, unsigned& r1, unsigned& r2,
                                       unsigned& r3, unsigned addr) {
    asm volatile("ldmatrix.sync.aligned.m8n8.x4.trans.shared.b16 {%0,%1,%2,%3}, [%4];"
                 : "=r"(r0), "=r"(r1), "=r"(r2), "=r"(r3) : "r"(addr));
}
__device__ __forceinline__ void ldsm2t(unsigned& r0, unsigned& r1, unsigned addr) {
    asm volatile("ldmatrix.sync.aligned.m8n8.x2.trans.shared.b16 {%0,%1}, [%2];"
                 : "=r"(r0), "=r"(r1) : "r"(addr));
}
__device__ __forceinline__ void mma16816(float* c, unsigned a0, unsigned a1,
                                         unsigned a2, unsigned a3,
                                         unsigned b0, unsigned b1) {
    asm volatile(
        "mma.sync.aligned.m16n8k16.row.col.f32.f16.f16.f32 "
        "{%0,%1,%2,%3}, {%4,%5,%6,%7}, {%8,%9}, {%0,%1,%2,%3};"
        : "+f"(c[0]), "+f"(c[1]), "+f"(c[2]), "+f"(c[3])
        : "r"(a0), "r"(a1), "r"(a2), "r"(a3), "r"(b0), "r"(b1));
}

// ---------------------------------------------------------------------------
// Shared prep phase (used by init_prep only): s_s[0..63] holds slot vector.
// ---------------------------------------------------------------------------
__device__ __forceinline__ void prep_phase(int b, int k, int t,
                                           float* s_s, float* s_q, float* s_st,
                                           const float* __restrict__ ln_g,
                                           const float* __restrict__ ln_b,
                                           const float* __restrict__ Wq,
                                           const float* __restrict__ Wk) {
    if (t < 32) {
        float a = s_s[t], c = s_s[32 + t];
        float s1 = a + c, s2 = a * a + c * c;
#pragma unroll
        for (int off = 16; off > 0; off >>= 1) {
            s1 += __shfl_xor_sync(0xFFFFFFFFu, s1, off);
            s2 += __shfl_xor_sync(0xFFFFFFFFu, s2, off);
        }
        if (t == 0) {
            float mean = s1 * (1.f / HH);
            float var = s2 * (1.f / HH) - mean * mean;
            s_st[0] = mean;
            s_st[1] = rsqrtf(var + 1e-5f);
        }
    }
    __syncthreads();
    if (t < HH) s_s[t] = (s_s[t] - s_st[0]) * s_st[1] * ln_g[t] + ln_b[t];
    __syncthreads();

    {
        int o = t >> 2, q4 = t & 3;
        const float4* w = (const float4*)(Wq + o * HH + q4 * 16);
        const float4* sv = (const float4*)(s_s + q4 * 16);
        float acc = 0.f;
#pragma unroll
        for (int i = 0; i < 4; i++) {
            float4 w4 = w[i], s4 = sv[i];
            acc += w4.x * s4.x + w4.y * s4.y + w4.z * s4.z + w4.w * s4.w;
        }
        acc += __shfl_xor_sync(0xFFFFFFFFu, acc, 1);
        acc += __shfl_xor_sync(0xFFFFFFFFu, acc, 2);
        if (q4 == 0) s_q[o] = acc * 0.125f;
    }
    __syncthreads();

    {
        float a0 = 0.f, a1 = 0.f, a2 = 0.f, a3 = 0.f;
#pragma unroll
        for (int h = 0; h < HH; h += 4) {
            a0 += s_q[h]     * Wk[(h)     * DD + t];
            a1 += s_q[h + 1] * Wk[(h + 1) * DD + t];
            a2 += s_q[h + 2] * Wk[(h + 2) * DD + t];
            a3 += s_q[h + 3] * Wk[(h + 3) * DD + t];
        }
        float val = (a0 + a1) + (a2 + a3);
        __half hi = __float2half_rn(val);
        __half lo = __float2half_rn(val - __half2float(hi));
        int ch = t >> 3, wi = t & 7;
        int rh = k, rl = 8 + k;
        g_qkh[b * 16 * DD + rh * DD + (((ch ^ (rh & 7)) << 3) | wi)] = hi;
        g_qkh[b * 16 * DD + rl * DD + (((ch ^ (rl & 7)) << 3) | wi)] = lo;
    }
}

// ---------------------------------------------------------------------------
// Kernel IP: fused slot init + qk padding zero + first prep. grid (KK, BB).
// ---------------------------------------------------------------------------
__global__ void __launch_bounds__(256)
init_prep_kernel(float* __restrict__ slots,
                 const float* __restrict__ noise,
                 const float* __restrict__ mu,
                 const float* __restrict__ sigma,
                 const float* __restrict__ ln_g,
                 const float* __restrict__ ln_b,
                 const float* __restrict__ Wq,
                 const float* __restrict__ Wk) {
    int k = blockIdx.x, b = blockIdx.y, t = threadIdx.x;
    __shared__ __align__(16) float s_s[HH];
    __shared__ __align__(16) float s_q[HH];
    __shared__ float s_st[2];

    if (k == 0) {  // zero qkh padding rows 6,7,14,15 for this b
        __half z = __ushort_as_half(0);
        g_qkh[b * 16 * DD + 6 * DD + t] = z;
        g_qkh[b * 16 * DD + 7 * DD + t] = z;
        g_qkh[b * 16 * DD + 14 * DD + t] = z;
        g_qkh[b * 16 * DD + 15 * DD + t] = z;
    }
    if (t < HH) {
        float sv = mu[t] + sigma[t] * noise[(b * KK + k) * HH + t];
        slots[(b * KK + k) * HH + t] = sv;
        s_s[t] = sv;
    }
    __syncthreads();
    prep_phase(b, k, t, s_s, s_q, s_st, ln_g, ln_b, Wq, Wk);
}

// ---------------------------------------------------------------------------
// Kernel LN: one-time LN(features) -> fp16. 2 rows per warp.
// ---------------------------------------------------------------------------
__global__ void __launch_bounds__(256)
ln_feat_kernel(const float* __restrict__ feat,
               const float* __restrict__ g,
               const float* __restrict__ bvec) {
    size_t r0 = (size_t)blockIdx.x * 16 + (threadIdx.x >> 5) * 2;
    int lane = threadIdx.x & 31;
    const float* p0 = feat + r0 * DD + 8 * lane;
    float4 a0 = ((const float4*)p0)[0];
    float4 c0 = ((const float4*)p0)[1];
    float4 a1 = ((const float4*)(p0 + DD))[0];
    float4 c1 = ((const float4*)(p0 + DD))[1];
    float f0[8] = {a0.x, a0.y, a0.z, a0.w, c0.x, c0.y, c0.z, c0.w};
    float f1[8] = {a1.x, a1.y, a1.z, a1.w, c1.x, c1.y, c1.z, c1.w};

    float s10 = 0.f, s20 = 0.f, s11 = 0.f, s21 = 0.f;
#pragma unroll
    for (int j = 0; j < 8; j++) {
        s10 += f0[j]; s20 += f0[j] * f0[j];
        s11 += f1[j]; s21 += f1[j] * f1[j];
    }
#pragma unroll
    for (int off = 16; off > 0; off >>= 1) {
        s10 += __shfl_xor_sync(0xFFFFFFFFu, s10, off);
        s20 += __shfl_xor_sync(0xFFFFFFFFu, s20, off);
        s11 += __shfl_xor_sync(0xFFFFFFFFu, s11, off);
        s21 += __shfl_xor_sync(0xFFFFFFFFu, s21, off);
    }
    float m0 = s10 * (1.f / DD), m1 = s11 * (1.f / DD);
    float r0s = rsqrtf(s20 * (1.f / DD) - m0 * m0 + 1e-5f);
    float r1s = rsqrtf(s21 * (1.f / DD) - m1 * m1 + 1e-5f);

    float4 ga = ((const float4*)(g + 8 * lane))[0];
    float4 gc = ((const float4*)(g + 8 * lane))[1];
    float4 ba = ((const float4*)(bvec + 8 * lane))[0];
    float4 bc = ((const float4*)(bvec + 8 * lane))[1];
    float gg[8] = {ga.x, ga.y, ga.z, ga.w, gc.x, gc.y, gc.z, gc.w};
    float bb[8] = {ba.x, ba.y, ba.z, ba.w, bc.x, bc.y, bc.z, bc.w};

    __half2 h0[4], h1[4];
#pragma unroll
    for (int j = 0; j < 4; j++) {
        float x0 = (f0[2 * j] - m0) * r0s * gg[2 * j] + bb[2 * j];
        float y0 = (f0[2 * j + 1] - m0) * r0s * gg[2 * j + 1] + bb[2 * j + 1];
        float x1 = (f1[2 * j] - m1) * r1s * gg[2 * j] + bb[2 * j];
        float y1 = (f1[2 * j + 1] - m1) * r1s * gg[2 * j + 1] + bb[2 * j + 1];
        h0[j] = __float22half2_rn(make_float2(x0, y0));
        h1[j] = __float22half2_rn(make_float2(x1, y1));
    }
    *(uint4*)(g_fh + r0 * DD + 8 * lane) = *(uint4*)h0;
    *(uint4*)(g_fh + (r0 + 1) * DD + 8 * lane) = *(uint4*)h1;
}

// ---------------------------------------------------------------------------
// Kernel A (hot): tensor-core attention streaming pass (round-5 config).
// grid (CHUNKS, BB) = 2048 blocks, 256 threads. 128 rows/block in 2 batches
// of 64; both batches cp.async'd upfront; P1(nb) overlapped with P3(nb-1).
// pdl=1: feature loads issued before griddepcontrol.wait (g_fh is immutable).
// ---------------------------------------------------------------------------
#define SMEM_F_BYTES (2 * BATCH * DD * 2)
#define SMEM_QK_OFF  SMEM_F_BYTES
#define SMEM_DOT_OFF (SMEM_QK_OFF + 16 * DD * 2)
#define SMEM_A_OFF   (SMEM_DOT_OFF + 2 * BATCH * 8 * 4)
#define SMEM_SP_OFF  (SMEM_A_OFF + 2 * BATCH * 8 * 2)
#define ATTN_SMEM    (SMEM_SP_OFF + 12 * 4)

__device__ __forceinline__ void issue_batch(const __half* gbase, int nb,
                                            char* smem, int tid) {
    const char* g = (const char*)(gbase + (size_t)nb * BATCH * DD);
    unsigned sbase = sptr(smem) + (nb & 1) * (BATCH * DD * 2);
#pragma unroll
    for (int it = 0; it < 8; it++) {
        int idx = tid + it * 256;
        int row = idx >> 5, j = idx & 31;
        unsigned dst = sbase + row * 512 + ((j ^ (row & 7)) << 4);
        const char* src = g + row * 512 + j * 16;
        asm volatile("cp.async.ca.shared.global [%0], [%1], 16;\n"
                     :: "r"(dst), "l"(src));
    }
    asm volatile("cp.async.commit_group;\n");
}

__global__ void __launch_bounds__(256, 2)
attn_kernel(int pdl) {
    extern __shared__ __align__(16) char smem[];
    __half* s_qk = (__half*)(smem + SMEM_QK_OFF);
    float* s_dot = (float*)(smem + SMEM_DOT_OFF);
    __half* s_a  = (__half*)(smem + SMEM_A_OFF);
    float* s_Sp  = (float*)(smem + SMEM_SP_OFF);

    int b = blockIdx.y, chunk = blockIdx.x;
    int tid = threadIdx.x, w = tid >> 5, lane = tid & 31;

    const __half* gbase = g_fh + ((size_t)b * NN + (size_t)chunk * ROWS_A) * DD;
    if (pdl) {
        // prologue independent of the previous kernel's outputs
        issue_batch(gbase, 0, smem, tid);
        issue_batch(gbase, 1, smem, tid);
        griddep_wait();   // previous update's g_qkh writes now visible
        const uint4* qs = (const uint4*)(g_qkh + b * 16 * DD);
        uint4* qd = (uint4*)s_qk;
        qd[tid] = qs[tid];
        qd[tid + 256] = qs[tid + 256];
    } else {
        const uint4* qs = (const uint4*)(g_qkh + b * 16 * DD);
        uint4* qd = (uint4*)s_qk;
        qd[tid] = qs[tid];
        qd[tid + 256] = qs[tid + 256];
        issue_batch(gbase, 0, smem, tid);
        issue_batch(gbase, 1, smem, tid);
    }

    unsigned s_f_u  = sptr(smem);
    unsigned s_qk_u = sptr(s_qk);
    unsigned s_a_u  = sptr(s_a);

    float accS[KK];
#pragma unroll
    for (int k = 0; k < KK; k++) accS[k] = 0.f;
    float u0[4] = {0.f, 0.f, 0.f, 0.f};
    float u1[4] = {0.f, 0.f, 0.f, 0.f};

    int g4 = lane >> 2, t4 = lane & 3;

    // P1 fragment index precompute
    int rt = w & 3, kh = w >> 2;
    int r0 = rt * 16;
    int arow = r0 + (lane & 15);
    int asel = lane >> 4;
    int brow = (lane & 7) + ((lane >> 4) << 3);
    int bsel = (lane >> 3) & 1;
    unsigned brow_base = s_qk_u + brow * 512;
    // P3 fragment index precompute
    int trow = (lane & 7) + ((lane >> 4) << 3);
    int tsel = (lane >> 3) & 1;

#pragma unroll
    for (int nb = 0; nb < NBATCH; nb++) {
        if (nb == 0) {
            asm volatile("cp.async.wait_group 1;\n" ::: "memory");
        } else {
            asm volatile("cp.async.wait_group 0;\n" ::: "memory");
        }
        __syncthreads();

        unsigned fb = s_f_u + (nb & 1) * (BATCH * DD * 2);

        // ---- P1: dots via mma on batch nb ----
        {
            float c[4] = {0.f, 0.f, 0.f, 0.f};
            unsigned arow_base = fb + arow * 512;
#pragma unroll
            for (int i = 0; i < 8; i++) {
                int kc = kh * 8 + i;
                unsigned a0, a1, a2, a3, bh0, bh1, bl0, bl1;
                int ach = 2 * kc + asel;
                ldsm4(a0, a1, a2, a3, arow_base + ((ach ^ (arow & 7)) << 4));
                int bch = 2 * kc + bsel;
                ldsm4(bh0, bh1, bl0, bl1, brow_base + ((bch ^ (brow & 7)) << 4));
                mma16816(c, a0, a1, a2, a3, bh0, bh1);
                mma16816(c, a0, a1, a2, a3, bl0, bl1);
            }
            float* dbase = s_dot + kh * (BATCH * 8);
            *(float2*)(dbase + (r0 + g4) * 8 + 2 * t4)     = make_float2(c[0], c[1]);
            *(float2*)(dbase + (r0 + g4 + 8) * 8 + 2 * t4) = make_float2(c[2], c[3]);
        }

        // ---- P3 for previous batch (no barrier needed: disjoint smem) ----
        if (nb > 0) {
            unsigned fp = s_f_u + ((nb - 1) & 1) * (BATCH * DD * 2);
            unsigned ap = s_a_u + ((nb - 1) & 1) * (BATCH * 8 * 2);
#pragma unroll
            for (int kc = 0; kc < 4; kc++) {
                unsigned b0, b1;
                ldsm2t(b0, b1, ap + (kc * 16 + (lane & 15)) * 16);
                int row = kc * 16 + trow;
                unsigned rbase = fp + row * 512;
                {
                    unsigned a0, a1, a2, a3;
                    int ch = w * 2 + tsel;
                    ldsm4t(a0, a1, a2, a3, rbase + ((ch ^ (row & 7)) << 4));
                    mma16816(u0, a0, a1, a2, a3, b0, b1);
                }
                {
                    unsigned a0, a1, a2, a3;
                    int ch = (w + 8) * 2 + tsel;
                    ldsm4t(a0, a1, a2, a3, rbase + ((ch ^ (row & 7)) << 4));
                    mma16816(u1, a0, a1, a2, a3, b0, b1);
                }
            }
        }
        __syncthreads();

        // ---- P2: per-row softmax (threads 0-63), a -> fp16 ----
        if (tid < 64) {
            int r = tid;
            float4 da = ((const float4*)(s_dot + r * 8))[0];
            float4 db = ((const float4*)(s_dot + r * 8))[1];
            float4 ea = ((const float4*)(s_dot + BATCH * 8 + r * 8))[0];
            float4 eb = ((const float4*)(s_dot + BATCH * 8 + r * 8))[1];
            float d[KK] = {da.x + ea.x, da.y + ea.y, da.z + ea.z,
                           da.w + ea.w, db.x + eb.x, db.y + eb.y};
            float mx = d[0];
#pragma unroll
            for (int k = 1; k < KK; k++) mx = fmaxf(mx, d[k]);
            float se = 0.f;
#pragma unroll
            for (int k = 0; k < KK; k++) { d[k] = __expf(d[k] - mx); se += d[k]; }
            float inv = 1.f / se;
            __half h[KK];
#pragma unroll
            for (int k = 0; k < KK; k++) {
                h[k] = __float2half_rn(d[k] * inv);
                accS[k] += __half2float(h[k]);
            }
            unsigned p0 = ((unsigned)__half_as_ushort(h[1]) << 16) | __half_as_ushort(h[0]);
            unsigned p1 = ((unsigned)__half_as_ushort(h[3]) << 16) | __half_as_ushort(h[2]);
            unsigned p2 = ((unsigned)__half_as_ushort(h[5]) << 16) | __half_as_ushort(h[4]);
            *(uint4*)(s_a + (nb & 1) * BATCH * 8 + r * 8) =
                make_uint4(p0, p1, p2, 0u);
        }
        __syncthreads();
    }

    // ---- final P3 for last batch ----
    {
        unsigned fp = s_f_u + ((NBATCH - 1) & 1) * (BATCH * DD * 2);
        unsigned ap = s_a_u + ((NBATCH - 1) & 1) * (BATCH * 8 * 2);
#pragma unroll
        for (int kc = 0; kc < 4; kc++) {
            unsigned b0, b1;
            ldsm2t(b0, b1, ap + (kc * 16 + (lane & 15)) * 16);
            int row = kc * 16 + trow;
            unsigned rbase = fp + row * 512;
            {
                unsigned a0, a1, a2, a3;
                int ch = w * 2 + tsel;
                ldsm4t(a0, a1, a2, a3, rbase + ((ch ^ (row & 7)) << 4));
                mma16816(u0, a0, a1, a2, a3, b0, b1);
            }
            {
                unsigned a0, a1, a2, a3;
                int ch = (w + 8) * 2 + tsel;
                ldsm4t(a0, a1, a2, a3, rbase + ((ch ^ (row & 7)) << 4));
                mma16816(u1, a0, a1, a2, a3, b0, b1);
            }
        }
    }

    // ---- epilogue: write U tiles ((b,k)-major layout) and S ----
    {
        if (t4 < 3) {
            int k0 = 2 * t4, k1 = 2 * t4 + 1;
            float* p0 = g_partU + ((size_t)(b * KK + k0) * CHUNKS + chunk) * DD;
            float* p1 = g_partU + ((size_t)(b * KK + k1) * CHUNKS + chunk) * DD;
            int d0 = w * 16;
            p0[d0 + g4]     = u0[0];
            p1[d0 + g4]     = u0[1];
            p0[d0 + 8 + g4] = u0[2];
            p1[d0 + 8 + g4] = u0[3];
            int d1 = (w + 8) * 16;
            p0[d1 + g4]     = u1[0];
            p1[d1 + g4]     = u1[1];
            p0[d1 + 8 + g4] = u1[2];
            p1[d1 + 8 + g4] = u1[3];
        }
    }
    if (tid < 64) {
#pragma unroll
        for (int off = 16; off > 0; off >>= 1)
#pragma unroll
            for (int k = 0; k < KK; k++)
                accS[k] += __shfl_xor_sync(0xFFFFFFFFu, accS[k], off);
        if (lane == 0)
#pragma unroll
            for (int k = 0; k < KK; k++) s_Sp[w * KK + k] = accS[k];
    }
    __syncthreads();
    if (tid < KK)
        g_partS[(b * KK + tid) * CHUNKS + chunk] = s_Sp[tid] + s_Sp[KK + tid];
    griddep_launch_dependents();
}

// ---------------------------------------------------------------------------
// Kernel C: one block per batch b (grid=BB, 256 threads). All 6 slots (k)
// interleaved in every phase (round-10 structure). PDL: weight L2-prefetch
// prologue runs before griddepcontrol.wait, overlapping attn's tail.
// ---------------------------------------------------------------------------
__global__ void __launch_bounds__(256)
update_kernel(float* __restrict__ slots,
              const float* __restrict__ Wv,
              const float* __restrict__ Wih,
              const float* __restrict__ Whh,
              const float* __restrict__ bih,
              const float* __restrict__ bhh,
              const float* __restrict__ lnm_g,
              const float* __restrict__ lnm_b,
              const float* __restrict__ W1,
              const float* __restrict__ b1,
              const float* __restrict__ W2,
              const float* __restrict__ b2,
              const float* __restrict__ lns_g,
              const float* __restrict__ lns_b,
              const float* __restrict__ Wq,
              const float* __restrict__ Wk,
              int do_prep) {
    int b = blockIdx.x, t = threadIdx.x;
    __shared__ __align__(16) float sU[KK][DD];
    __shared__ __align__(16) float sxv[KK][HH];
    __shared__ __align__(16) float shp[KK][HH];
    __shared__ float sgrz[KK][2 * HH];
    __shared__ float sgin[KK][HH], sghn[KK][HH];
    __shared__ __align__(16) float shn[KK][HH];
    __shared__ __align__(16) float smm[KK][HH];
    __shared__ __align__(16) float sm1[KK][2 * HH];
    __shared__ __align__(16) float sout[KK][HH];
    __shared__ float sq[KK][HH];
    __shared__ float sst[KK][4];

    // ---- PDL prologue: warm L2 with all weights (independent of attn) ----
    prefetch_array(Wv, HH * DD, t, 256);
    prefetch_array(Wih, 3 * HH * HH, t, 256);
    prefetch_array(Whh, 3 * HH * HH, t, 256);
    prefetch_array(W1, 2 * HH * HH, t, 256);
    prefetch_array(W2, 2 * HH * HH, t, 256);
    prefetch_array(Wq, HH * HH, t, 256);
    prefetch_array(Wk, HH * DD, t, 256);
    griddep_wait();   // attn's partU/partS/qk writes now visible

    // Phase A: gather partials (contiguous per (b,k); c-ascending order)
#pragma unroll
    for (int k = 0; k < KK; k++) {
        const float* base = g_partU + (size_t)(b * KK + k) * CHUNKS * DD;
        float u = 0.f;
#pragma unroll
        for (int c = 0; c < CHUNKS; c++)
            u += base[c * DD + t];
        sU[k][t] = u;
    }
    if (t < 192) {
        int k = t >> 5, lane = t & 31;
        float S = g_partS[(b * KK + k) * CHUNKS + lane];
#pragma unroll
        for (int off = 16; off > 0; off >>= 1)
            S += __shfl_xor_sync(0xFFFFFFFFu, S, off);
        if (lane == 0) sst[k][0] = 1.f / (S + 1e-8f);
    }
    for (int i = t; i < KK * HH; i += 256) {
        int k = i >> 6, h = i & 63;
        shp[k][h] = slots[(b * KK + k) * HH + h];
    }
    __syncthreads();

    // Phase B: xv = (Wv @ U) * invS  (4 thr/output; weight loaded once)
    {
        int o = t >> 2, q = t & 3;
        const float4* wv = (const float4*)(Wv + o * DD + q * 64);
        float a0[KK], a1[KK];
#pragma unroll
        for (int k = 0; k < KK; k++) { a0[k] = 0.f; a1[k] = 0.f; }
#pragma unroll
        for (int i = 0; i < 16; i++) {
            float4 w4 = wv[i];
#pragma unroll
            for (int k = 0; k < KK; k++) {
                float4 u4 = ((const float4*)(&sU[k][q * 64]))[i];
                a0[k] += w4.x * u4.x + w4.z * u4.z;
                a1[k] += w4.y * u4.y + w4.w * u4.w;
            }
        }
#pragma unroll
        for (int k = 0; k < KK; k++) {
            float acc = a0[k] + a1[k];
            acc += __shfl_xor_sync(0xFFFFFFFFu, acc, 1);
            acc += __shfl_xor_sync(0xFFFFFFFFu, acc, 2);
            if (q == 0) sxv[k][o] = acc * sst[k][0];
        }
    }
    __syncthreads();

    // Phase C: GRU gate GEMVs (thread = gate row; weights loaded once)
    if (t < 192) {
        int gate = t >> 6, idx = t & 63;
        const float4* wi = (const float4*)(Wih + t * HH);
        const float4* wh = (const float4*)(Whh + t * HH);
        float gi[KK], gh[KK];
        float bi = bih[t], bh = bhh[t];
#pragma unroll
        for (int k = 0; k < KK; k++) { gi[k] = bi; gh[k] = bh; }
#pragma unroll
        for (int i = 0; i < 16; i++) {
            float4 w4 = wi[i], v4 = wh[i];
#pragma unroll
            for (int k = 0; k < KK; k++) {
                float4 x4 = ((const float4*)sxv[k])[i];
                float4 h4 = ((const float4*)shp[k])[i];
                gi[k] += w4.x * x4.x + w4.y * x4.y + w4.z * x4.z + w4.w * x4.w;
                gh[k] += v4.x * h4.x + v4.y * h4.y + v4.z * h4.z + v4.w * h4.w;
            }
        }
#pragma unroll
        for (int k = 0; k < KK; k++) {
            if (gate < 2) sgrz[k][t] = gi[k] + gh[k];
            else { sgin[k][idx] = gi[k]; sghn[k][idx] = gh[k]; }
        }
    }
    __syncthreads();

    // Phase D: gate nonlinearity + h update
    for (int i = t; i < KK * HH; i += 256) {
        int k = i >> 6, h = i & 63;
        float r = 1.f / (1.f + __expf(-sgrz[k][h]));
        float z = 1.f / (1.f + __expf(-sgrz[k][64 + h]));
        float n = tanhf(sgin[k][h] + r * sghn[k][h]);
        shn[k][h] = (1.f - z) * n + z * shp[k][h];
    }
    __syncthreads();

    // LN over new slots (warp per k)
    if (t < 192) {
        int k = t >> 5, lane = t & 31;
        float a = shn[k][lane], c = shn[k][32 + lane];
        float s1 = a + c, s2 = a * a + c * c;
#pragma unroll
        for (int off = 16; off > 0; off >>= 1) {
            s1 += __shfl_xor_sync(0xFFFFFFFFu, s1, off);
            s2 += __shfl_xor_sync(0xFFFFFFFFu, s2, off);
        }
        if (lane == 0) {
            float mean = s1 * (1.f / HH);
            float var = s2 * (1.f / HH) - mean * mean;
            sst[k][1] = mean;
            sst[k][2] = rsqrtf(var + 1e-5f);
        }
    }
    __syncthreads();
    for (int i = t; i < KK * HH; i += 256) {
        int k = i >> 6, h = i & 63;
        smm[k][h] = (shn[k][h] - sst[k][1]) * sst[k][2] * lnm_g[h] + lnm_b[h];
    }
    __syncthreads();

    // Phase E: MLP layer 1 (2 thr/output; weights loaded once)
    {
        int o = t >> 1, hf = t & 1;
        const float4* w1 = (const float4*)(W1 + o * HH + hf * 32);
        float acc[KK];
#pragma unroll
        for (int k = 0; k < KK; k++) acc[k] = 0.f;
#pragma unroll
        for (int i = 0; i < 8; i++) {
            float4 w4 = w1[i];
#pragma unroll
            for (int k = 0; k < KK; k++) {
                float4 m4 = ((const float4*)(&smm[k][hf * 32]))[i];
                acc[k] += w4.x * m4.x + w4.y * m4.y + w4.z * m4.z + w4.w * m4.w;
            }
        }
        float bo = b1[o];
#pragma unroll
        for (int k = 0; k < KK; k++) {
            float a = acc[k];
            a += __shfl_xor_sync(0xFFFFFFFFu, a, 1);
            if (hf == 0) sm1[k][o] = fmaxf(a + bo, 0.f);
        }
    }
    __syncthreads();

    // Phase F: MLP layer 2 + residual
    {
        int o = t >> 2, q = t & 3;
        const float4* w2 = (const float4*)(W2 + o * 2 * HH + q * 32);
        float acc[KK];
#pragma unroll
        for (int k = 0; k < KK; k++) acc[k] = 0.f;
#pragma unroll
        for (int i = 0; i < 8; i++) {
            float4 w4 = w2[i];
#pragma unroll
            for (int k = 0; k < KK; k++) {
                float4 m4 = ((const float4*)(&sm1[k][q * 32]))[i];
                acc[k] += w4.x * m4.x + w4.y * m4.y + w4.z * m4.z + w4.w * m4.w;
            }
        }
        float bo = b2[o];
#pragma unroll
        for (int k = 0; k < KK; k++) {
            float a = acc[k];
            a += __shfl_xor_sync(0xFFFFFFFFu, a, 1);
            a += __shfl_xor_sync(0xFFFFFFFFu, a, 2);
            if (q == 0) {
                float out = shn[k][o] + a + bo;
                slots[(b * KK + k) * HH + o] = out;
                sout[k][o] = out;
            }
        }
    }

    if (!do_prep) { griddep_launch_dependents(); return; }
    __syncthreads();

    // ---- fused prep: LN(slots) -> q = Wq@s*0.125 -> qk hi/lo ----
    if (t < 192) {
        int k = t >> 5, lane = t & 31;
        float a = sout[k][lane], c = sout[k][32 + lane];
        float s1 = a + c, s2 = a * a + c * c;
#pragma unroll
        for (int off = 16; off > 0; off >>= 1) {
            s1 += __shfl_xor_sync(0xFFFFFFFFu, s1, off);
            s2 += __shfl_xor_sync(0xFFFFFFFFu, s2, off);
        }
        if (lane == 0) {
            float mean = s1 * (1.f / HH);
            float var = s2 * (1.f / HH) - mean * mean;
            sst[k][1] = mean;
            sst[k][2] = rsqrtf(var + 1e-5f);
        }
    }
    __syncthreads();
    for (int i = t; i < KK * HH; i += 256) {
        int k = i >> 6, h = i & 63;
        smm[k][h] = (sout[k][h] - sst[k][1]) * sst[k][2] * lns_g[h] + lns_b[h];
    }
    __syncthreads();

    {
        int o = t >> 2, q4 = t & 3;
        const float4* w = (const float4*)(Wq + o * HH + q4 * 16);
        float acc[KK];
#pragma unroll
        for (int k = 0; k < KK; k++) acc[k] = 0.f;
#pragma unroll
        for (int i = 0; i < 4; i++) {
            float4 w4 = w[i];
#pragma unroll
            for (int k = 0; k < KK; k++) {
                float4 s4 = ((const float4*)(&smm[k][q4 * 16]))[i];
                acc[k] += w4.x * s4.x + w4.y * s4.y + w4.z * s4.z + w4.w * s4.w;
            }
        }
#pragma unroll
        for (int k = 0; k < KK; k++) {
            float a = acc[k];
            a += __shfl_xor_sync(0xFFFFFFFFu, a, 1);
            a += __shfl_xor_sync(0xFFFFFFFFu, a, 2);
            if (q4 == 0) sq[k][o] = a * 0.125f;
        }
    }
    __syncthreads();

    {
        float a0[KK], a1[KK], a2[KK], a3[KK];
#pragma unroll
        for (int k = 0; k < KK; k++) { a0[k] = 0.f; a1[k] = 0.f; a2[k] = 0.f; a3[k] = 0.f; }
#pragma unroll
        for (int h = 0; h < HH; h += 4) {
            float wk0 = Wk[(h)     * DD + t];
            float wk1 = Wk[(h + 1) * DD + t];
            float wk2 = Wk[(h + 2) * DD + t];
            float wk3 = Wk[(h + 3) * DD + t];
#pragma unroll
            for (int k = 0; k < KK; k++) {
                a0[k] += sq[k][h]     * wk0;
                a1[k] += sq[k][h + 1] * wk1;
                a2[k] += sq[k][h + 2] * wk2;
                a3[k] += sq[k][h + 3] * wk3;
            }
        }
        int ch = t >> 3, wi = t & 7;
#pragma unroll
        for (int k = 0; k < KK; k++) {
            float val = (a0[k] + a1[k]) + (a2[k] + a3[k]);
            __half hi = __float2half_rn(val);
            __half lo = __float2half_rn(val - __half2float(hi));
            int rh = k, rl = 8 + k;
            g_qkh[b * 16 * DD + rh * DD + (((ch ^ (rh & 7)) << 3) | wi)] = hi;
            g_qkh[b * 16 * DD + rl * DD + (((ch ^ (rl & 7)) << 3) | wi)] = lo;
        }
    }
    griddep_launch_dependents();
}

// ---------------------------------------------------------------------------
extern "C" void kernel_launch(void* const* d_in, const int* in_sizes, int n_in,
                              void* d_out, int out_size) {
    const float* features   = (const float*)d_in[0];
    const float* slot_noise = (const float*)d_in[1];
    const float* slot_mu    = (const float*)d_in[2];
    const float* slot_sigma = (const float*)d_in[3];
    const float* ln_feat_g  = (const float*)d_in[4];
    const float* ln_feat_b  = (const float*)d_in[5];
    const float* ln_slot_g  = (const float*)d_in[6];
    const float* ln_slot_b  = (const float*)d_in[7];
    const float* ln_mlp_g   = (const float*)d_in[8];
    const float* ln_mlp_b   = (const float*)d_in[9];
    const float* Wk         = (const float*)d_in[10];
    const float* Wv         = (const float*)d_in[11];
    const float* Wq         = (const float*)d_in[12];
    const float* W_ih       = (const float*)d_in[13];
    const float* W_hh       = (const float*)d_in[14];
    const float* b_ih       = (const float*)d_in[15];
    const float* b_hh       = (const float*)d_in[16];
    const float* mlp_W1     = (const float*)d_in[17];
    const float* mlp_b1     = (const float*)d_in[18];
    const float* mlp_W2     = (const float*)d_in[19];
    const float* mlp_b2     = (const float*)d_in[20];

    float* slots = (float*)d_out;  // [B, K, H] lives in the output buffer

    cudaFuncSetAttribute(attn_kernel,
                         cudaFuncAttributeMaxDynamicSharedMemorySize,
                         ATTN_SMEM);

    dim3 gridSmall(KK, BB);
    dim3 gridA(CHUNKS, BB);

    cudaLaunchAttribute pss[1];
    pss[0].id = cudaLaunchAttributeProgrammaticStreamSerialization;
    pss[0].val.programmaticStreamSerializationAllowed = 1;

    init_prep_kernel<<<gridSmall, 256>>>(slots, slot_noise, slot_mu, slot_sigma,
                                         ln_slot_g, ln_slot_b, Wq, Wk);

    {   // ln overlaps init (fully independent)
        cudaLaunchConfig_t cfg = {};
        cfg.gridDim = dim3(BB * NN / 16);
        cfg.blockDim = dim3(256);
        cfg.attrs = pss; cfg.numAttrs = 1;
        cudaLaunchKernelEx(&cfg, ln_feat_kernel, features, ln_feat_g, ln_feat_b);
    }

    for (int it = 0; it < 3; it++) {
        if (it == 0) {
            attn_kernel<<<gridA, 256, ATTN_SMEM>>>(0);  // plain: must see ln
        } else {
            cudaLaunchConfig_t cfg = {};
            cfg.gridDim = gridA; cfg.blockDim = dim3(256);
            cfg.dynamicSmemBytes = ATTN_SMEM;
            cfg.attrs = pss; cfg.numAttrs = 1;
            cudaLaunchKernelEx(&cfg, attn_kernel, 1);
        }
        {
            cudaLaunchConfig_t cfg = {};
            cfg.gridDim = dim3(BB); cfg.blockDim = dim3(256);
            cfg.attrs = pss; cfg.numAttrs = 1;
            cudaLaunchKernelEx(&cfg, update_kernel, slots, Wv, W_ih, W_hh,
                               b_ih, b_hh, ln_mlp_g, ln_mlp_b, mlp_W1, mlp_b1,
                               mlp_W2, mlp_b2, ln_slot_g, ln_slot_b,
                               Wq, Wk, it < 2 ? 1 : 0);
        }
    }
}